// round 4
// baseline (speedup 1.0000x reference)
#include <cuda_runtime.h>
#include <cstdint>

#define E_TOT 43234
#define NQ 64              // q index: 4 d-values per q
#define QC 8               // q per staged chunk
#define ROW 33             // padded chunk row stride (ulonglong2 units)
#define STAGE_U2 (2 * QC * ROW)   // 528 u2 per buffer (re rows 0-7, im rows 8-15)
#define NTHR 256
#define NBLK 296
#define NTILES ((E_TOT + 31) / 32)  // 1352

// Rotated+NEGATED head: g_head[b*512 + q*8 + {0..3}] = -re(4q..4q+3), {4..7} = -im(...)
__device__ float g_head[32 * 512];

// ---------- f32x2 packed helpers (sm_103a) ----------
static __device__ __forceinline__ unsigned long long addx2(unsigned long long a, unsigned long long b) {
    unsigned long long r; asm("add.rn.f32x2 %0, %1, %2;" : "=l"(r) : "l"(a), "l"(b)); return r;
}
static __device__ __forceinline__ unsigned long long mulx2(unsigned long long a, unsigned long long b) {
    unsigned long long r; asm("mul.rn.f32x2 %0, %1, %2;" : "=l"(r) : "l"(a), "l"(b)); return r;
}
static __device__ __forceinline__ unsigned long long fmax2(unsigned long long a, unsigned long long b, unsigned long long c) {
    unsigned long long r; asm("fma.rn.f32x2 %0, %1, %2, %3;" : "=l"(r) : "l"(a), "l"(b), "l"(c)); return r;
}
static __device__ __forceinline__ void unpack2(unsigned long long v, float& lo, float& hi) {
    asm("mov.b64 {%0, %1}, %2;" : "=f"(lo), "=f"(hi) : "l"(v));
}
static __device__ __forceinline__ float sqrt_approx(float x) {
    float r; asm("sqrt.approx.f32 %0, %1;" : "=f"(r) : "f"(x)); return r;
}

// ---------- prep: rotate head, negate, write broadcast-friendly layout ----------
__global__ void prep_kernel(const float* __restrict__ head, const float* __restrict__ rel) {
    int b = blockIdx.x, d = threadIdx.x;
    float re_h = head[b * 512 + d];
    float im_h = head[b * 512 + 256 + d];
    float phase = rel[b * 256 + d] * 100.53096491487338f;  // rel * 32*pi
    float s, c; sincosf(phase, &s, &c);
    float re_rot = re_h * c - im_h * s;
    float im_rot = re_h * s + im_h * c;
    int q = d >> 2, j = d & 3;
    g_head[b * 512 + q * 8 + j]     = -re_rot;
    g_head[b * 512 + q * 8 + 4 + j] = -im_rot;
}

// ---------- main: CTA = 32-entity tile; lane = entity; warp w handles b in [4w, 4w+4) ----------
__global__ void __launch_bounds__(NTHR, 2)
dist_kernel(const float* __restrict__ ent, float* __restrict__ out) {
    extern __shared__ ulonglong2 sm[];
    ulonglong2* stage = sm;                 // double buffer: 2 * 528 u2 = 16896 B
    ulonglong2* Hs    = sm + 2 * STAGE_U2;  // head: 4096 u2 = 65536 B (128B-aligned)

    const int tid = threadIdx.x, wid = tid >> 5, lane = tid & 31;

    {   // load head table (64KB) once per CTA
        const float4* src = reinterpret_cast<const float4*>(g_head);
        float4* dst = reinterpret_cast<float4*>(Hs);
        for (int i = tid; i < 4096; i += NTHR) dst[i] = src[i];
    }
    __syncthreads();

    for (int tile = blockIdx.x; tile < NTILES; tile += NBLK) {
        int e0 = tile * 32; if (e0 > E_TOT - 32) e0 = E_TOT - 32;  // clamped tail: identical rewrites
        const ulonglong2* base = reinterpret_cast<const ulonglong2*>(ent) + (size_t)e0 * 128;

        float acc0[4] = {0, 0, 0, 0}, acc1[4] = {0, 0, 0, 0};

        // prologue: stage chunk 0 into buffer 0 (coalesced cp.async, transposed pad-33 layout)
#pragma unroll
        for (int r = 0; r < 2; r++) {
            int j = tid + r * NTHR;                     // 512 items: j = t*16 + k
            int t = j >> 4, k = j & 15;                 // k = isIm*8 + qq
            const ulonglong2* src = base + t * 128 + (k >> 3) * 64 + (k & 7);
            uint32_t s = (uint32_t)__cvta_generic_to_shared(stage + k * ROW + t);
            asm volatile("cp.async.cg.shared.global [%0], [%1], 16;" :: "r"(s), "l"(src));
        }
        asm volatile("cp.async.commit_group;");
        asm volatile("cp.async.wait_group 0;" ::: "memory");
        __syncthreads();

        int cur = 0;
        for (int qc = 0; qc < NQ; qc += QC) {
            // prefetch next chunk into the other buffer (overlapped with compute)
            if (qc + QC < NQ) {
                ulonglong2* nbuf = stage + (cur ^ 1) * STAGE_U2;
#pragma unroll
                for (int r = 0; r < 2; r++) {
                    int j = tid + r * NTHR;
                    int t = j >> 4, k = j & 15;
                    const ulonglong2* src = base + t * 128 + (k >> 3) * 64 + (qc + QC) + (k & 7);
                    uint32_t s = (uint32_t)__cvta_generic_to_shared(nbuf + k * ROW + t);
                    asm volatile("cp.async.cg.shared.global [%0], [%1], 16;" :: "r"(s), "l"(src));
                }
            }
            asm volatile("cp.async.commit_group;");

            const ulonglong2* S = stage + cur * STAGE_U2;
            const ulonglong2* Hb = Hs + (wid * 4) * 128;
#pragma unroll 2
            for (int qq = 0; qq < QC; qq++) {
                const int q = qc + qq;
                // lane's entity quads for d = 4q..4q+3 (conflict-free LDS.128)
                ulonglong2 ere = S[qq * ROW + lane];
                ulonglong2 eim = S[(QC + qq) * ROW + lane];
#pragma unroll
                for (int bb = 0; bb < 4; bb++) {
                    // warp-uniform 16B broadcasts of (-rot) head quads
                    const ulonglong2 hre = Hb[bb * 128 + 2 * q];
                    const ulonglong2 him = Hb[bb * 128 + 2 * q + 1];
                    unsigned long long a0 = addx2(ere.x, hre.x);   // t_re - rot_re (pairs d0,d1)
                    unsigned long long a1 = addx2(ere.y, hre.y);   // pairs d2,d3
                    unsigned long long c0 = addx2(eim.x, him.x);
                    unsigned long long c1 = addx2(eim.y, him.y);
                    unsigned long long p0 = fmax2(c0, c0, mulx2(a0, a0));
                    unsigned long long p1 = fmax2(c1, c1, mulx2(a1, a1));
                    float x0, x1, y0, y1;
                    unpack2(p0, x0, x1);
                    unpack2(p1, y0, y1);
                    acc0[bb] += sqrt_approx(x0) + sqrt_approx(y0);
                    acc1[bb] += sqrt_approx(x1) + sqrt_approx(y1);
                }
            }
            asm volatile("cp.async.wait_group 0;" ::: "memory");
            __syncthreads();
            cur ^= 1;
        }

        // coalesced stores: 4 rows of 32 consecutive entities
#pragma unroll
        for (int bb = 0; bb < 4; bb++)
            out[(size_t)(wid * 4 + bb) * E_TOT + e0 + lane] = 6.0f - (acc0[bb] + acc1[bb]);
    }
}

extern "C" void kernel_launch(void* const* d_in, const int* in_sizes, int n_in,
                              void* d_out, int out_size) {
    const float* head = (const float*)d_in[0];   // (32, 512)
    const float* rel  = (const float*)d_in[1];   // (32, 256)
    const float* ent  = (const float*)d_in[2];   // (43234, 512)
    float* out = (float*)d_out;                  // (32, 43234)

    const int smem = (2 * STAGE_U2 + 4096) * 16;  // 82432 B
    cudaFuncSetAttribute(dist_kernel, cudaFuncAttributeMaxDynamicSharedMemorySize, smem);

    prep_kernel<<<32, 256>>>(head, rel);
    dist_kernel<<<NBLK, NTHR, smem>>>(ent, out);
}